// round 4
// baseline (speedup 1.0000x reference)
#include <cuda_runtime.h>
#include <math.h>

// ---- fixed problem shapes (from reference setup_inputs) ----
#define Bq   8
#define Hh   64
#define Wd   64
#define Cc   32
#define KHc  7
#define KWc  7
#define EHc  5
#define EWc  5
#define Hoc  58
#define Woc  58
#define Ff   64
#define Kk   800            // EH*EW*C
#define Pp   26912          // B*Ho*Wo
#define Ppad 27008          // 211 * 128 (GEMM BM padding)
#define EPSf 1e-7f

// ---- scratch (static __device__ globals: zero-initialized, no allocs) ----
__device__ float g_rot[(size_t)Ppad * Kk];   // [pixel][k] rotated-patch matrix
__device__ float g_wt[Kk * Ff];              // W transposed: [k][f]

// ------------------------------------------------------------------
// Kernel 1: transpose W (64,5,5,32) -> g_wt[k][f], k=(eh*5+ew)*32+c
// ------------------------------------------------------------------
__global__ void wt_kernel(const float* __restrict__ W) {
    int idx = blockIdx.x * blockDim.x + threadIdx.x;
    if (idx < Kk * Ff) {
        int f = idx / Kk;
        int k = idx % Kk;
        g_wt[k * Ff + f] = W[idx];
    }
}

// ------------------------------------------------------------------
// Kernel 2: per-pixel orientation + bilinear rotation -> g_rot
// One warp per pixel; lane == channel.
// ------------------------------------------------------------------
__global__ void rot_kernel(const float* __restrict__ x) {
    const int warp = threadIdx.x >> 5;
    const int lane = threadIdx.x & 31;
    const int pix  = blockIdx.x * 4 + warp;   // Pp % 4 == 0

    __shared__ float sp[4][49 * 33];          // pitch 33: conflict-free
    float* patch = sp[warp];

    const int w = pix % Woc;
    const int t = pix / Woc;
    const int h = t % Hoc;
    const int b = t / Hoc;

    const float* xb = x + (((size_t)b * Hh + h) * Wd + w) * Cc;

    // load 7x7 patch (channel = lane, fully coalesced) + moment partials
    float sI = 0.f, sR = 0.f, sC = 0.f;
#pragma unroll
    for (int p = 0; p < 49; ++p) {
        const int i = p / 7, j = p % 7;
        float v = xb[((size_t)i * Wd + j) * Cc + lane];
        patch[p * 33 + lane] = v;
        sI += v;
        sR += (float)i * v;
        sC += (float)j * v;
    }
    // butterfly reduce -> every lane holds totals
#pragma unroll
    for (int off = 16; off; off >>= 1) {
        sI += __shfl_xor_sync(0xffffffffu, sI, off);
        sR += __shfl_xor_sync(0xffffffffu, sR, off);
        sC += __shfl_xor_sync(0xffffffffu, sC, off);
    }

    const float denom = sI + EPSf;
    const float cr = sR / denom - 3.0f;
    const float cc = sC / denom - 3.0f;
    const float ang = atan2f(cr, cc + EPSf);
    const float cA = cosf(ang), sA = sinf(ang);
    const float scale = 1.0f + EPSf;
    const float xo = (6.0f - (cA * 6.0f - sA * 6.0f)) * 0.5f;
    const float yo = (6.0f - (sA * 6.0f + cA * 6.0f)) * 0.5f;
    const float a0 =  cA / scale, a1 = -sA / scale, a2 = xo / scale;
    const float a3 =  sA / scale, a4 =  cA / scale, a5 = yo / scale;

    float* outp = g_rot + (size_t)pix * Kk;

#pragma unroll
    for (int eh = 0; eh < 5; ++eh) {
        const float yg = (float)(eh + 1);   // crop PAD=1
#pragma unroll
        for (int ew = 0; ew < 5; ++ew) {
            const float xg  = (float)(ew + 1);
            const float xin = a0 * xg + a1 * yg + a2;
            const float yin = a3 * xg + a4 * yg + a5;
            const float x0f = floorf(xin), y0f = floorf(yin);
            const float wx1 = xin - x0f, wx0 = 1.0f - wx1;
            const float wy1 = yin - y0f, wy0 = 1.0f - wy1;
            const int x0 = (int)x0f, y0 = (int)y0f;
            const int x1 = x0 + 1,  y1 = y0 + 1;
            const bool vx0 = (x0 >= 0) & (x0 < 7);
            const bool vx1 = (x1 >= 0) & (x1 < 7);
            const bool vy0 = (y0 >= 0) & (y0 < 7);
            const bool vy1 = (y1 >= 0) & (y1 < 7);
            const float w00 = (vy0 & vx0) ? wy0 * wx0 : 0.f;
            const float w01 = (vy0 & vx1) ? wy0 * wx1 : 0.f;
            const float w10 = (vy1 & vx0) ? wy1 * wx0 : 0.f;
            const float w11 = (vy1 & vx1) ? wy1 * wx1 : 0.f;
            const int x0c = min(max(x0, 0), 6), x1c = min(max(x1, 0), 6);
            const int y0c = min(max(y0, 0), 6), y1c = min(max(y1, 0), 6);
            float r = w00 * patch[(y0c * 7 + x0c) * 33 + lane]
                    + w01 * patch[(y0c * 7 + x1c) * 33 + lane]
                    + w10 * patch[(y1c * 7 + x0c) * 33 + lane]
                    + w11 * patch[(y1c * 7 + x1c) * 33 + lane];
            outp[(eh * 5 + ew) * 32 + lane] = r;
        }
    }
}

// ------------------------------------------------------------------
// Kernel 3: out[P x 64] = g_rot[P x 800] * g_wt[800 x 64] + bias
// BM=128, BN=64, BK=16, 256 threads, 8x4 microtile (FMA-bound)
// ------------------------------------------------------------------
#define BM 128
#define BN 64
#define BK 16

__global__ __launch_bounds__(256) void gemm_kernel(const float* __restrict__ bias,
                                                   float* __restrict__ out) {
    __shared__ float As[BK][BM];   // transposed A tile
    __shared__ float Bs[BK][BN];

    const int tid = threadIdx.x;
    const int m0  = blockIdx.x * BM;
    const int tx  = tid & 15;      // n-group: 16 * 4 = 64
    const int ty  = tid >> 4;      // m-group: 16 * 8 = 128

    float acc[8][4];
#pragma unroll
    for (int i = 0; i < 8; ++i)
#pragma unroll
        for (int j = 0; j < 4; ++j) acc[i][j] = 0.f;

    const int ar = tid >> 2;           // 0..63 (A row group)
    const int ak = (tid & 3) * 4;      // 0,4,8,12
    const int br = tid >> 4;           // 0..15 (B k-row)
    const int bc = (tid & 15) * 4;     // B col

    for (int k0 = 0; k0 < Kk; k0 += BK) {
        // load A tile (128 x 16), float4 along k, store transposed
#pragma unroll
        for (int rr = 0; rr < 2; ++rr) {
            const int m = ar + rr * 64;
            float4 av = *(const float4*)(g_rot + (size_t)(m0 + m) * Kk + k0 + ak);
            As[ak + 0][m] = av.x;
            As[ak + 1][m] = av.y;
            As[ak + 2][m] = av.z;
            As[ak + 3][m] = av.w;
        }
        // load B tile (16 x 64), coalesced float4
        *(float4*)(&Bs[br][bc]) = *(const float4*)(g_wt + (k0 + br) * Ff + bc);
        __syncthreads();

#pragma unroll
        for (int kk = 0; kk < BK; ++kk) {
            const float4 b4  = *(const float4*)(&Bs[kk][tx * 4]);
            const float4 a4a = *(const float4*)(&As[kk][ty * 8]);
            const float4 a4b = *(const float4*)(&As[kk][ty * 8 + 4]);
            const float av[8] = {a4a.x, a4a.y, a4a.z, a4a.w,
                                 a4b.x, a4b.y, a4b.z, a4b.w};
            const float bv[4] = {b4.x, b4.y, b4.z, b4.w};
#pragma unroll
            for (int i = 0; i < 8; ++i)
#pragma unroll
                for (int j = 0; j < 4; ++j)
                    acc[i][j] = fmaf(av[i], bv[j], acc[i][j]);
        }
        __syncthreads();
    }

    // epilogue: + bias, guarded store
    const int nb = tx * 4;
    const float4 bb = *(const float4*)(bias + nb);
#pragma unroll
    for (int i = 0; i < 8; ++i) {
        const int m = m0 + ty * 8 + i;
        if (m < Pp) {
            float4 r;
            r.x = acc[i][0] + bb.x;
            r.y = acc[i][1] + bb.y;
            r.z = acc[i][2] + bb.z;
            r.w = acc[i][3] + bb.w;
            *(float4*)(out + (size_t)m * Ff + nb) = r;
        }
    }
}

// ------------------------------------------------------------------
extern "C" void kernel_launch(void* const* d_in, const int* in_sizes, int n_in,
                              void* d_out, int out_size) {
    const float* x    = (const float*)d_in[0];
    const float* W    = (const float*)d_in[1];
    const float* bias = (const float*)d_in[2];
    float* out        = (float*)d_out;

    wt_kernel<<<(Kk * Ff + 255) / 256, 256>>>(W);
    rot_kernel<<<Pp / 4, 128>>>(x);
    gemm_kernel<<<(Pp + BM - 1) / BM, 256>>>(bias, out);
}

// round 7
// speedup vs baseline: 1.0096x; 1.0096x over previous
#include <cuda_runtime.h>
#include <cstdint>
#include <math.h>

// ---- fixed problem shapes (from reference setup_inputs) ----
#define Bq   8
#define Hh   64
#define Wd   64
#define Cc   32
#define Hoc  58
#define Woc  58
#define Ff   64
#define Kk   800            // EH*EW*C
#define Pp   26912          // B*Ho*Wo
#define Ppad 27008          // 211 * 128 (GEMM BM padding)
#define EPSf 1e-7f

// ---- scratch (static __device__ globals: zero-initialized, no allocs) ----
__device__ float g_rot[(size_t)Ppad * Kk];   // [pixel][k] rotated-patch matrix
__device__ float g_wt[Kk * Ff];              // W transposed: [k][f]

// ---- packed f32x2 helpers (base Blackwell ISA, no 'a' target needed) ----
__device__ __forceinline__ unsigned long long pack2(float lo, float hi) {
    unsigned long long d;
    asm("mov.b64 %0, {%1, %2};" : "=l"(d) : "f"(lo), "f"(hi));
    return d;
}
__device__ __forceinline__ void unpack2(unsigned long long v, float& lo, float& hi) {
    asm("mov.b64 {%0, %1}, %2;" : "=f"(lo), "=f"(hi) : "l"(v));
}
__device__ __forceinline__ unsigned long long fma2(unsigned long long a,
                                                   unsigned long long b,
                                                   unsigned long long c) {
    unsigned long long d;
    asm("fma.rn.f32x2 %0, %1, %2, %3;" : "=l"(d) : "l"(a), "l"(b), "l"(c));
    return d;
}

// ------------------------------------------------------------------
// Kernel 1: transpose W (64,5,5,32) -> g_wt[k][f], k=(eh*5+ew)*32+c
// ------------------------------------------------------------------
__global__ void wt_kernel(const float* __restrict__ W) {
    int idx = blockIdx.x * blockDim.x + threadIdx.x;
    if (idx < Kk * Ff) {
        int f = idx / Kk;
        int k = idx % Kk;
        g_wt[k * Ff + f] = W[idx];
    }
}

// ------------------------------------------------------------------
// Kernel 2: per-pixel orientation + bilinear rotation -> g_rot
// One warp per pixel; lane == channel.
// ------------------------------------------------------------------
__global__ void rot_kernel(const float* __restrict__ x) {
    const int warp = threadIdx.x >> 5;
    const int lane = threadIdx.x & 31;
    const int pix  = blockIdx.x * 4 + warp;   // Pp % 4 == 0

    __shared__ float sp[4][49 * 33];          // pitch 33: conflict-free
    float* patch = sp[warp];

    const int w = pix % Woc;
    const int t = pix / Woc;
    const int h = t % Hoc;
    const int b = t / Hoc;

    const float* xb = x + (((size_t)b * Hh + h) * Wd + w) * Cc;

    float sI = 0.f, sR = 0.f, sC = 0.f;
#pragma unroll
    for (int p = 0; p < 49; ++p) {
        const int i = p / 7, j = p % 7;
        float v = xb[((size_t)i * Wd + j) * Cc + lane];
        patch[p * 33 + lane] = v;
        sI += v;
        sR += (float)i * v;
        sC += (float)j * v;
    }
#pragma unroll
    for (int off = 16; off; off >>= 1) {
        sI += __shfl_xor_sync(0xffffffffu, sI, off);
        sR += __shfl_xor_sync(0xffffffffu, sR, off);
        sC += __shfl_xor_sync(0xffffffffu, sC, off);
    }

    const float denom = sI + EPSf;
    const float cr = sR / denom - 3.0f;
    const float cc = sC / denom - 3.0f;
    const float ang = atan2f(cr, cc + EPSf);
    const float cA = cosf(ang), sA = sinf(ang);
    const float scale = 1.0f + EPSf;
    const float xo = (6.0f - (cA * 6.0f - sA * 6.0f)) * 0.5f;
    const float yo = (6.0f - (sA * 6.0f + cA * 6.0f)) * 0.5f;
    const float a0 =  cA / scale, a1 = -sA / scale, a2 = xo / scale;
    const float a3 =  sA / scale, a4 =  cA / scale, a5 = yo / scale;

    float* outp = g_rot + (size_t)pix * Kk;

#pragma unroll
    for (int eh = 0; eh < 5; ++eh) {
        const float yg = (float)(eh + 1);   // crop PAD=1
#pragma unroll
        for (int ew = 0; ew < 5; ++ew) {
            const float xg  = (float)(ew + 1);
            const float xin = a0 * xg + a1 * yg + a2;
            const float yin = a3 * xg + a4 * yg + a5;
            const float x0f = floorf(xin), y0f = floorf(yin);
            const float wx1 = xin - x0f, wx0 = 1.0f - wx1;
            const float wy1 = yin - y0f, wy0 = 1.0f - wy1;
            const int x0 = (int)x0f, y0 = (int)y0f;
            const int x1 = x0 + 1,  y1 = y0 + 1;
            const bool vx0 = (x0 >= 0) & (x0 < 7);
            const bool vx1 = (x1 >= 0) & (x1 < 7);
            const bool vy0 = (y0 >= 0) & (y0 < 7);
            const bool vy1 = (y1 >= 0) & (y1 < 7);
            const float w00 = (vy0 & vx0) ? wy0 * wx0 : 0.f;
            const float w01 = (vy0 & vx1) ? wy0 * wx1 : 0.f;
            const float w10 = (vy1 & vx0) ? wy1 * wx0 : 0.f;
            const float w11 = (vy1 & vx1) ? wy1 * wx1 : 0.f;
            const int x0c = min(max(x0, 0), 6), x1c = min(max(x1, 0), 6);
            const int y0c = min(max(y0, 0), 6), y1c = min(max(y1, 0), 6);
            float r = w00 * patch[(y0c * 7 + x0c) * 33 + lane]
                    + w01 * patch[(y0c * 7 + x1c) * 33 + lane]
                    + w10 * patch[(y1c * 7 + x0c) * 33 + lane]
                    + w11 * patch[(y1c * 7 + x1c) * 33 + lane];
            outp[(eh * 5 + ew) * 32 + lane] = r;
        }
    }
}

// ------------------------------------------------------------------
// Kernel 3: out[P x 64] = g_rot[P x 800] * g_wt[800 x 64] + bias
// BM=128, BN=64, BK=16, 256 threads, 8x4 microtile.
// Inner product uses packed fma.rn.f32x2 (SASS FFMA2): accumulators
// packed along M-pairs -> 16 FFMA2 + 8 ALU-pipe packs per k (was 32 FFMA).
// ------------------------------------------------------------------
#define BM 128
#define BN 64
#define BK 16

__global__ __launch_bounds__(256) void gemm_kernel(const float* __restrict__ bias,
                                                   float* __restrict__ out) {
    __shared__ float As[BK][BM];   // transposed A tile
    __shared__ float Bs[BK][BN];

    const int tid = threadIdx.x;
    const int m0  = blockIdx.x * BM;
    const int tx  = tid & 15;      // n-group: 16 * 4 = 64
    const int ty  = tid >> 4;      // m-group: 16 * 8 = 128

    // acc2[p][j]: packed fp32 pair (m = ty*8+2p, ty*8+2p+1), col j
    unsigned long long acc2[4][4];
#pragma unroll
    for (int p = 0; p < 4; ++p)
#pragma unroll
        for (int j = 0; j < 4; ++j) acc2[p][j] = pack2(0.f, 0.f);

    const int ar = tid >> 2;           // 0..63 (A row group)
    const int ak = (tid & 3) * 4;      // 0,4,8,12
    const int br = tid >> 4;           // 0..15 (B k-row)
    const int bc = (tid & 15) * 4;     // B col

    for (int k0 = 0; k0 < Kk; k0 += BK) {
        // load A tile (128 x 16), float4 along k, store transposed
#pragma unroll
        for (int rr = 0; rr < 2; ++rr) {
            const int m = ar + rr * 64;
            float4 av = *(const float4*)(g_rot + (size_t)(m0 + m) * Kk + k0 + ak);
            As[ak + 0][m] = av.x;
            As[ak + 1][m] = av.y;
            As[ak + 2][m] = av.z;
            As[ak + 3][m] = av.w;
        }
        // load B tile (16 x 64), coalesced float4
        *(float4*)(&Bs[br][bc]) = *(const float4*)(g_wt + (k0 + br) * Ff + bc);
        __syncthreads();

#pragma unroll
        for (int kk = 0; kk < BK; ++kk) {
            const float4 b4  = *(const float4*)(&Bs[kk][tx * 4]);
            const float4 a4a = *(const float4*)(&As[kk][ty * 8]);
            const float4 a4b = *(const float4*)(&As[kk][ty * 8 + 4]);

            unsigned long long ap[4];
            ap[0] = pack2(a4a.x, a4a.y);
            ap[1] = pack2(a4a.z, a4a.w);
            ap[2] = pack2(a4b.x, a4b.y);
            ap[3] = pack2(a4b.z, a4b.w);

            unsigned long long bd[4];
            bd[0] = pack2(b4.x, b4.x);
            bd[1] = pack2(b4.y, b4.y);
            bd[2] = pack2(b4.z, b4.z);
            bd[3] = pack2(b4.w, b4.w);

#pragma unroll
            for (int p = 0; p < 4; ++p)
#pragma unroll
                for (int j = 0; j < 4; ++j)
                    acc2[p][j] = fma2(ap[p], bd[j], acc2[p][j]);
        }
        __syncthreads();
    }

    // epilogue: unpack, + bias, guarded store
    const int nb = tx * 4;
    const float4 bb = *(const float4*)(bias + nb);
#pragma unroll
    for (int p = 0; p < 4; ++p) {
        float lo[4], hi[4];
#pragma unroll
        for (int j = 0; j < 4; ++j) unpack2(acc2[p][j], lo[j], hi[j]);

        const int mA = m0 + ty * 8 + 2 * p;
        if (mA < Pp) {
            float4 r;
            r.x = lo[0] + bb.x;
            r.y = lo[1] + bb.y;
            r.z = lo[2] + bb.z;
            r.w = lo[3] + bb.w;
            *(float4*)(out + (size_t)mA * Ff + nb) = r;
        }
        const int mB = mA + 1;
        if (mB < Pp) {
            float4 r;
            r.x = hi[0] + bb.x;
            r.y = hi[1] + bb.y;
            r.z = hi[2] + bb.z;
            r.w = hi[3] + bb.w;
            *(float4*)(out + (size_t)mB * Ff + nb) = r;
        }
    }
}

// ------------------------------------------------------------------
extern "C" void kernel_launch(void* const* d_in, const int* in_sizes, int n_in,
                              void* d_out, int out_size) {
    const float* x    = (const float*)d_in[0];
    const float* W    = (const float*)d_in[1];
    const float* bias = (const float*)d_in[2];
    float* out        = (float*)d_out;

    wt_kernel<<<(Kk * Ff + 255) / 256, 256>>>(W);
    rot_kernel<<<Pp / 4, 128>>>(x);
    gemm_kernel<<<(Pp + BM - 1) / BM, 256>>>(bias, out);
}